// round 1
// baseline (speedup 1.0000x reference)
#include <cuda_runtime.h>
#include <math.h>

#define B_ 2
#define T_ 4096
#define E_ 2048
#define E2_ 4096
#define H_ 16
#define KD_ 128
#define HD_ 256
#define CH_ 256
#define NC_ 16
#define NCHUNKS (B_*NC_*H_)   // 512

// ---------------- scratch (device globals; no allocation allowed) ----------------
__device__ float g_q [B_*T_*E_];            // q pre/post rotary, [B,T,H,KD] packed as [B*T, E]
__device__ float g_k [B_*T_*E_];            // k pre/post rotary (pre-scaled by KD^-0.5)
__device__ float g_v [B_*T_*E2_];           // v  [B*T, 2E]
__device__ float g_gt[B_*T_*E2_];           // g  [B*T, 2E]
__device__ float g_qk[(size_t)NCHUNKS*CH_*CH_];    // raw qk*mask per chunk
__device__ float g_isc[NCHUNKS*CH_];               // row |qk| sums (unclipped)
__device__ float g_inner[(size_t)NCHUNKS*CH_*HD_]; // inner_output (already / inner_scale)
__device__ float g_kv [(size_t)NCHUNKS*KD_*HD_];   // per-chunk kv
__device__ float g_kvr[(size_t)NCHUNKS*KD_*HD_];   // scanned kv_rec (already / cross_scale... no: state/scale)
__device__ float g_csc[NCHUNKS*HD_];               // cross_scale per v (clipped)
__device__ float g_ro [B_*T_*E2_];                 // silu(g)*LN(out)

// ---------------- generic SGEMM: C[M,N] = (A[M,K] @ W[N,K]^T + bias) * scale ----------------
__global__ __launch_bounds__(256)
void sgemm_wt(const float* __restrict__ A, const float* __restrict__ W,
              const float* __restrict__ bias, float* __restrict__ C,
              int M, int Nn, int K, float scale)
{
    __shared__ float As[8][128];
    __shared__ float Bs[8][128];
    const int bx = blockIdx.x, by = blockIdx.y;
    const int tid = threadIdx.x;
    const int tc = tid & 15, tr = tid >> 4;
    const float* Ab = A + (size_t)(by * 128) * K;
    const float* Wb = W + (size_t)(bx * 128) * K;
    const int lr = tid >> 1;          // 0..127
    const int lk = (tid & 1) * 4;     // 0 or 4
    float acc[8][8] = {};
    for (int k0 = 0; k0 < K; k0 += 8) {
        float4 a4 = *(const float4*)(Ab + (size_t)lr * K + k0 + lk);
        float4 w4 = *(const float4*)(Wb + (size_t)lr * K + k0 + lk);
        As[lk+0][lr] = a4.x; As[lk+1][lr] = a4.y; As[lk+2][lr] = a4.z; As[lk+3][lr] = a4.w;
        Bs[lk+0][lr] = w4.x; Bs[lk+1][lr] = w4.y; Bs[lk+2][lr] = w4.z; Bs[lk+3][lr] = w4.w;
        __syncthreads();
        #pragma unroll
        for (int kk = 0; kk < 8; kk++) {
            float rm[8], rn[8];
            #pragma unroll
            for (int i = 0; i < 8; i++) rm[i] = As[kk][tr*8+i];
            #pragma unroll
            for (int j = 0; j < 8; j++) rn[j] = Bs[kk][tc*8+j];
            #pragma unroll
            for (int i = 0; i < 8; i++)
                #pragma unroll
                for (int j = 0; j < 8; j++)
                    acc[i][j] += rm[i] * rn[j];
        }
        __syncthreads();
    }
    #pragma unroll
    for (int i = 0; i < 8; i++) {
        int row = by*128 + tr*8 + i;
        #pragma unroll
        for (int j = 0; j < 8; j++) {
            int col = bx*128 + tc*8 + j;
            C[(size_t)row * Nn + col] = (acc[i][j] + bias[col]) * scale;
        }
    }
}

// ---------------- rotary (in-place on q and k) ----------------
__global__ void rotary_k(float* __restrict__ q, float* __restrict__ k,
                         const float* __restrict__ sn, const float* __restrict__ cs)
{
    int p = blockIdx.x * blockDim.x + threadIdx.x;     // pair index
    if (p >= B_*T_*E_/2) return;
    int f = p * 2;
    int row = f / E_;
    int t = row % T_;
    int col = f % E_;
    int d = col % KD_;                 // even
    float2 qv = *(float2*)(q + (size_t)f);
    float2 kv = *(float2*)(k + (size_t)f);
    float c0 = cs[t*KD_ + d],   c1 = cs[t*KD_ + d + 1];
    float s0 = sn[t*KD_ + d],   s1 = sn[t*KD_ + d + 1];
    float2 qo, ko;
    qo.x = qv.x * c0 - qv.y * s0;
    qo.y = qv.y * c1 + qv.x * s1;
    ko.x = kv.x * c0 - kv.y * s0;
    ko.y = kv.y * c1 + kv.x * s1;
    *(float2*)(q + (size_t)f) = qo;
    *(float2*)(k + (size_t)f) = ko;
}

// ---------------- qk = qr @ kr^T * mask, plus row |.| sums ----------------
// block: 128 q-rows x 256 d-cols of one (b,n,h) chunk; 512 threads, 8x8/thread
__global__ __launch_bounds__(512)
void qk_kernel(const float* __restrict__ mask)
{
    __shared__ float As[8][128];
    __shared__ float Bs[8][256];
    const int z = blockIdx.x;
    const int chunk = z >> 1, half = z & 1;
    const int b = chunk / (NC_*H_);
    const int n = (chunk / H_) % NC_;
    const int h = chunk % H_;
    const int row0 = half * 128;
    const int tid = threadIdx.x;
    const int tr = tid >> 5, tc = tid & 31;            // 16 x 32
    const float* Ab = g_q + ((size_t)(b*T_ + n*CH_ + row0)) * E_ + h*KD_;
    const float* Bb = g_k + ((size_t)(b*T_ + n*CH_)) * E_ + h*KD_;
    const int a_row = tid >> 2, a_k = (tid & 3) * 2;
    const int b_row = tid >> 1, b_k = (tid & 1) * 4;
    float acc[8][8] = {};
    for (int k0 = 0; k0 < KD_; k0 += 8) {
        float2 a2 = *(const float2*)(Ab + (size_t)a_row * E_ + k0 + a_k);
        float4 b4 = *(const float4*)(Bb + (size_t)b_row * E_ + k0 + b_k);
        As[a_k  ][a_row] = a2.x;
        As[a_k+1][a_row] = a2.y;
        Bs[b_k+0][b_row] = b4.x; Bs[b_k+1][b_row] = b4.y;
        Bs[b_k+2][b_row] = b4.z; Bs[b_k+3][b_row] = b4.w;
        __syncthreads();
        #pragma unroll
        for (int kk = 0; kk < 8; kk++) {
            float rm[8], rn[8];
            #pragma unroll
            for (int i = 0; i < 8; i++) rm[i] = As[kk][tr*8+i];
            #pragma unroll
            for (int j = 0; j < 8; j++) rn[j] = Bs[kk][tc*8+j];
            #pragma unroll
            for (int i = 0; i < 8; i++)
                #pragma unroll
                for (int j = 0; j < 8; j++)
                    acc[i][j] += rm[i] * rn[j];
        }
        __syncthreads();
    }
    float* qko = g_qk + (size_t)chunk * (CH_*CH_) + (size_t)row0 * CH_;
    const float* mrow = mask + (size_t)h * (CH_*CH_) + (size_t)row0 * CH_;
    #pragma unroll
    for (int i = 0; i < 8; i++) {
        int r = tr*8 + i;
        float psum = 0.f;
        #pragma unroll
        for (int j = 0; j < 8; j++) {
            int c = tc*8 + j;
            float v = acc[i][j] * mrow[(size_t)r*CH_ + c];
            qko[(size_t)r*CH_ + c] = v;
            psum += fabsf(v);
        }
        #pragma unroll
        for (int o = 16; o > 0; o >>= 1)
            psum += __shfl_xor_sync(0xffffffffu, psum, o);
        if (tc == 0) g_isc[chunk*CH_ + row0 + r] = psum;
    }
}

// ---------------- inner = (qk / clip(isc,1)) @ vc ----------------
__global__ __launch_bounds__(512)
void inner_kernel()
{
    __shared__ float As[8][128];
    __shared__ float Bs[8][256];
    const int z = blockIdx.x;
    const int chunk = z >> 1, half = z & 1;
    const int b = chunk / (NC_*H_);
    const int n = (chunk / H_) % NC_;
    const int h = chunk % H_;
    const int row0 = half * 128;
    const int tid = threadIdx.x;
    const int tr = tid >> 5, tc = tid & 31;
    const float* Ab = g_qk + (size_t)chunk * (CH_*CH_) + (size_t)row0 * CH_;
    const float* Vb = g_v + ((size_t)(b*T_ + n*CH_)) * E2_ + h*HD_;
    const int a_row = tid >> 2, a_k = (tid & 3) * 2;
    const int bkk = tid >> 6, bv = (tid & 63) * 4;
    float acc[8][8] = {};
    for (int k0 = 0; k0 < CH_; k0 += 8) {
        float2 a2 = *(const float2*)(Ab + (size_t)a_row * CH_ + k0 + a_k);
        As[a_k  ][a_row] = a2.x;
        As[a_k+1][a_row] = a2.y;
        float4 b4 = *(const float4*)(Vb + (size_t)(k0 + bkk) * E2_ + bv);
        *(float4*)&Bs[bkk][bv] = b4;
        __syncthreads();
        #pragma unroll
        for (int kk = 0; kk < 8; kk++) {
            float rm[8], rn[8];
            #pragma unroll
            for (int i = 0; i < 8; i++) rm[i] = As[kk][tr*8+i];
            #pragma unroll
            for (int j = 0; j < 8; j++) rn[j] = Bs[kk][tc*8+j];
            #pragma unroll
            for (int i = 0; i < 8; i++)
                #pragma unroll
                for (int j = 0; j < 8; j++)
                    acc[i][j] += rm[i] * rn[j];
        }
        __syncthreads();
    }
    float* op = g_inner + (size_t)chunk * (CH_*HD_) + (size_t)row0 * HD_;
    #pragma unroll
    for (int i = 0; i < 8; i++) {
        int r = tr*8 + i;
        float inv = 1.f / fmaxf(g_isc[chunk*CH_ + row0 + r], 1.f);
        #pragma unroll
        for (int j = 0; j < 8; j++)
            op[(size_t)r*HD_ + tc*8 + j] = acc[i][j] * inv;
    }
}

// ---------------- kv[k,v] = sum_c kr[c,k]*maskrow[c]*vc[c,v] ----------------
__global__ __launch_bounds__(512)
void kv_kernel(const float* __restrict__ mask)
{
    __shared__ float As[8][128];   // [cc][k]
    __shared__ float Bs[8][256];   // [cc][v]
    const int chunk = blockIdx.x;
    const int b = chunk / (NC_*H_);
    const int n = (chunk / H_) % NC_;
    const int h = chunk % H_;
    const int tid = threadIdx.x;
    const int tr = tid >> 5, tc = tid & 31;            // 16 x 32 -> 128 x 256 out
    const float* Kb = g_k + ((size_t)(b*T_ + n*CH_)) * E_ + h*KD_;
    const float* Vb = g_v + ((size_t)(b*T_ + n*CH_)) * E2_ + h*HD_;
    const float* wrow = mask + (size_t)h * (CH_*CH_) + (size_t)(CH_-1) * CH_;
    const int acc_cc = tid >> 6;          // 0..7
    const int a_kcol = (tid & 63) * 2;
    const int b_vcol = (tid & 63) * 4;
    float acc[8][8] = {};
    for (int c0 = 0; c0 < CH_; c0 += 8) {
        float w = wrow[c0 + acc_cc];
        float2 a2 = *(const float2*)(Kb + (size_t)(c0 + acc_cc) * E_ + a_kcol);
        As[acc_cc][a_kcol  ] = a2.x * w;
        As[acc_cc][a_kcol+1] = a2.y * w;
        float4 b4 = *(const float4*)(Vb + (size_t)(c0 + acc_cc) * E2_ + b_vcol);
        *(float4*)&Bs[acc_cc][b_vcol] = b4;
        __syncthreads();
        #pragma unroll
        for (int kk = 0; kk < 8; kk++) {
            float rm[8], rn[8];
            #pragma unroll
            for (int i = 0; i < 8; i++) rm[i] = As[kk][tr*8+i];
            #pragma unroll
            for (int j = 0; j < 8; j++) rn[j] = Bs[kk][tc*8+j];
            #pragma unroll
            for (int i = 0; i < 8; i++)
                #pragma unroll
                for (int j = 0; j < 8; j++)
                    acc[i][j] += rm[i] * rn[j];
        }
        __syncthreads();
    }
    float* op = g_kv + (size_t)chunk * (KD_*HD_);
    #pragma unroll
    for (int i = 0; i < 8; i++)
        #pragma unroll
        for (int j = 0; j < 8; j++)
            op[(size_t)(tr*8+i)*HD_ + tc*8 + j] = acc[i][j];
}

// ---------------- cross-chunk scan (per b,h,16-v-slab) ----------------
__global__ __launch_bounds__(256)
void scan_kernel(const float* __restrict__ cdec)
{
    const int vb = blockIdx.x & 15;
    const int bh = blockIdx.x >> 4;
    const int b = bh / H_, h = bh % H_;
    const int v0 = vb * 16;
    const int tid = threadIdx.x;
    const int v = tid & 15;
    const int kg = tid >> 4;           // 0..15, 8 kd each
    float s[8] = {0,0,0,0,0,0,0,0};
    __shared__ float sc[16];
    __shared__ float red[256];
    if (tid < 16) sc[tid] = 1.f;
    __syncthreads();
    const float cd = cdec[h];
    for (int n = 0; n < NC_; n++) {
        const int chunk = (b*NC_ + n)*H_ + h;
        const size_t zo = (size_t)chunk * (KD_*HD_);
        float invsc = 1.f / sc[v];
        #pragma unroll
        for (int i = 0; i < 8; i++)
            g_kvr[zo + (size_t)(kg*8+i)*HD_ + v0 + v] = s[i] * invsc;
        if (tid < 16) g_csc[chunk*HD_ + v0 + tid] = sc[tid];
        float p = 0.f;
        #pragma unroll
        for (int i = 0; i < 8; i++) {
            s[i] = s[i]*cd + g_kv[zo + (size_t)(kg*8+i)*HD_ + v0 + v];
            p += fabsf(s[i]);
        }
        red[tid] = p;
        __syncthreads();
        if (tid < 16) {
            float sum = 0.f;
            #pragma unroll
            for (int j = 0; j < 16; j++) sum += red[j*16 + tid];
            sc[tid] = fmaxf(sum, 1.f);
        }
        __syncthreads();
    }
}

// ------- cross = (qr*idec) @ kv_rec; combine + LayerNorm + silu(g) gate -------
__global__ __launch_bounds__(512)
void cross_kernel(const float* __restrict__ idec)
{
    __shared__ float As[8][128];
    __shared__ float Bs[8][256];
    const int z = blockIdx.x;
    const int chunk = z >> 1, half = z & 1;
    const int b = chunk / (NC_*H_);
    const int n = (chunk / H_) % NC_;
    const int h = chunk % H_;
    const int row0 = half * 128;
    const int tid = threadIdx.x;
    const int tr = tid >> 5, tc = tid & 31;
    const float* Ab = g_q + ((size_t)(b*T_ + n*CH_ + row0)) * E_ + h*KD_;
    const float* Bb = g_kvr + (size_t)chunk * (KD_*HD_);
    const int a_row = tid >> 2, a_k = (tid & 3) * 2;
    const int bkk = tid >> 6, bv = (tid & 63) * 4;
    const float aw = idec[h*CH_ + row0 + a_row];
    float acc[8][8] = {};
    for (int k0 = 0; k0 < KD_; k0 += 8) {
        float2 a2 = *(const float2*)(Ab + (size_t)a_row * E_ + k0 + a_k);
        As[a_k  ][a_row] = a2.x * aw;
        As[a_k+1][a_row] = a2.y * aw;
        float4 b4 = *(const float4*)(Bb + (size_t)(k0 + bkk) * HD_ + bv);
        *(float4*)&Bs[bkk][bv] = b4;
        __syncthreads();
        #pragma unroll
        for (int kk = 0; kk < 8; kk++) {
            float rm[8], rn[8];
            #pragma unroll
            for (int i = 0; i < 8; i++) rm[i] = As[kk][tr*8+i];
            #pragma unroll
            for (int j = 0; j < 8; j++) rn[j] = Bs[kk][tc*8+j];
            #pragma unroll
            for (int i = 0; i < 8; i++)
                #pragma unroll
                for (int j = 0; j < 8; j++)
                    acc[i][j] += rm[i] * rn[j];
        }
        __syncthreads();
    }
    const float* innp = g_inner + (size_t)chunk * (CH_*HD_) + (size_t)row0 * HD_;
    const float* cscp = g_csc + chunk*HD_;
    const float* gp   = g_gt + ((size_t)(b*T_ + n*CH_ + row0)) * E2_ + h*HD_;
    float* rop        = g_ro + ((size_t)(b*T_ + n*CH_ + row0)) * E2_ + h*HD_;
    #pragma unroll
    for (int i = 0; i < 8; i++) {
        int r = tr*8 + i;
        float isc = fmaxf(g_isc[chunk*CH_ + row0 + r], 1.f);
        float rsum = 0.f, rsq = 0.f;
        #pragma unroll
        for (int j = 0; j < 8; j++) {
            int c = tc*8 + j;
            float o = innp[(size_t)r*HD_ + c] / cscp[c] + acc[i][j] / isc;
            acc[i][j] = o;
            rsum += o;
            rsq  += o*o;
        }
        #pragma unroll
        for (int off = 16; off > 0; off >>= 1) {
            rsum += __shfl_xor_sync(0xffffffffu, rsum, off);
            rsq  += __shfl_xor_sync(0xffffffffu, rsq,  off);
        }
        float mean = rsum * (1.f/HD_);
        float var  = rsq  * (1.f/HD_) - mean*mean;
        float rstd = rsqrtf(var + 1e-5f);
        #pragma unroll
        for (int j = 0; j < 8; j++) {
            int c = tc*8 + j;
            float gv = gp[(size_t)r*E2_ + c];
            float si = gv / (1.f + expf(-gv));
            rop[(size_t)r*E2_ + c] = si * (acc[i][j] - mean) * rstd;
        }
    }
}

// ---------------- launch ----------------
extern "C" void kernel_launch(void* const* d_in, const int* in_sizes, int n_in,
                              void* d_out, int out_size)
{
    const float* x    = (const float*)d_in[0];
    const float* sn   = (const float*)d_in[1];
    const float* cs   = (const float*)d_in[2];
    const float* mask = (const float*)d_in[3];
    const float* cdec = (const float*)d_in[4];
    const float* idec = (const float*)d_in[5];
    const float* Wq = (const float*)d_in[6];
    const float* bq = (const float*)d_in[7];
    const float* Wk = (const float*)d_in[8];
    const float* bk = (const float*)d_in[9];
    const float* Wv = (const float*)d_in[10];
    const float* bv = (const float*)d_in[11];
    const float* Wg = (const float*)d_in[12];
    const float* bg = (const float*)d_in[13];
    const float* Wo = (const float*)d_in[14];
    const float* bo = (const float*)d_in[15];
    float* out = (float*)d_out;

    float *qp, *kp, *vp, *gp, *rop;
    cudaGetSymbolAddress((void**)&qp,  g_q);
    cudaGetSymbolAddress((void**)&kp,  g_k);
    cudaGetSymbolAddress((void**)&vp,  g_v);
    cudaGetSymbolAddress((void**)&gp,  g_gt);
    cudaGetSymbolAddress((void**)&rop, g_ro);

    const int M = B_*T_;
    dim3 g16(E_/128,  M/128);
    dim3 g32(E2_/128, M/128);
    const float kscale = 1.0f / sqrtf((float)KD_);

    sgemm_wt<<<g16, 256>>>(x, Wq, bq, qp, M, E_,  E_, 1.f);
    sgemm_wt<<<g16, 256>>>(x, Wk, bk, kp, M, E_,  E_, kscale);
    sgemm_wt<<<g32, 256>>>(x, Wv, bv, vp, M, E2_, E_, 1.f);
    sgemm_wt<<<g32, 256>>>(x, Wg, bg, gp, M, E2_, E_, 1.f);
    rotary_k<<<(B_*T_*E_/2 + 255)/256, 256>>>(qp, kp, sn, cs);
    qk_kernel   <<<2*NCHUNKS, 512>>>(mask);
    inner_kernel<<<2*NCHUNKS, 512>>>();
    kv_kernel   <<<NCHUNKS,   512>>>(mask);
    scan_kernel <<<B_*H_*(HD_/16), 256>>>(cdec);
    cross_kernel<<<2*NCHUNKS, 512>>>(idec);
    sgemm_wt<<<dim3(E_/128, M/128), 256>>>(rop, Wo, bo, out, M, E_, E2_, 1.f);
}

// round 3
// speedup vs baseline: 2.3946x; 2.3946x over previous
#include <cuda_runtime.h>
#include <math.h>
#include <stdint.h>

#define B_ 2
#define T_ 4096
#define E_ 2048
#define E2_ 4096
#define H_ 16
#define KD_ 128
#define HD_ 256
#define CH_ 256
#define NC_ 16
#define NCHUNKS (B_*NC_*H_)   // 512

// ================= scratch =================
__device__ float g_q [B_*T_*E_];
__device__ float g_k [B_*T_*E_];
__device__ float g_v [B_*T_*E2_];
__device__ float g_gt[B_*T_*E2_];
__device__ float g_qk[(size_t)NCHUNKS*CH_*CH_];
__device__ float g_isc[NCHUNKS*CH_];
__device__ float g_inner[(size_t)NCHUNKS*CH_*HD_];
__device__ float g_kv [(size_t)NCHUNKS*KD_*HD_];
__device__ float g_kvr[(size_t)NCHUNKS*KD_*HD_];
__device__ float g_csc[NCHUNKS*HD_];
__device__ float g_ro [B_*T_*E2_];

// ================= helpers =================
__device__ __forceinline__ uint32_t smem_u32(const void* p) {
    uint32_t a;
    asm("{ .reg .u64 t; cvta.to.shared.u64 t, %1; cvt.u32.u64 %0, t; }" : "=r"(a) : "l"(p));
    return a;
}
__device__ __forceinline__ uint32_t f2tf(float x) {
    uint32_t r; asm("cvt.rna.tf32.f32 %0, %1;" : "=r"(r) : "f"(x)); return r;
}
__device__ __forceinline__ void cp16(uint32_t dst, const void* src) {
    asm volatile("cp.async.cg.shared.global [%0], [%1], 16;" :: "r"(dst), "l"(src));
}
__device__ __forceinline__ void cp_commit() { asm volatile("cp.async.commit_group;"); }
__device__ __forceinline__ void mma_tf32(float c[4], const uint32_t a[4], const uint32_t b[2]) {
    asm volatile(
        "mma.sync.aligned.m16n8k8.row.col.f32.tf32.tf32.f32 "
        "{%0,%1,%2,%3}, {%4,%5,%6,%7}, {%8,%9}, {%0,%1,%2,%3};"
        : "+f"(c[0]), "+f"(c[1]), "+f"(c[2]), "+f"(c[3])
        : "r"(a[0]), "r"(a[1]), "r"(a[2]), "r"(a[3]), "r"(b[0]), "r"(b[1]));
}

// ================= tensor-core GEMM: C = (A @ W^T + bias) * scale =================
// A [M,K] row-major f32, W [N,K] row-major f32. Block tile 128x128, K-slab 32.
// 8 warps as 2(M) x 4(N); warp tile 64x32; mma m16n8k8 tf32.
#define BM 128
#define BN 128
#define BK 32
#define PAD 36
#define TILE_F (128*PAD)
#define TILE_BYTES (TILE_F*4)
#define GEMM_SMEM (4*TILE_BYTES)   // A0,A1,B0,B1 = 73728 bytes

__global__ void __launch_bounds__(256)
gemm_mma(const float* __restrict__ A, const float* __restrict__ W,
         const float* __restrict__ bias, float* __restrict__ C,
         int K, int Ncols, float scale)
{
    extern __shared__ __align__(128) float sm[];
    const int tid = threadIdx.x;
    const int wid = tid >> 5, lane = tid & 31;
    const int wm = wid & 1, wn = wid >> 1;       // 2 x 4 warp grid
    const int g = lane >> 2, q = lane & 3;
    const int bx = blockIdx.x, by = blockIdx.y;

    const float* Ab = A + (size_t)(by * BM) * K;
    const float* Wb = W + (size_t)(bx * BN) * K;

    const uint32_t sbase = smem_u32(sm);
    const int lr = tid >> 1;                 // 0..127 (row)
    const int lc = (tid & 1) * 16;           // first float col of this thread's 4 float4s

    const int NS = K / BK;
    float acc[4][4][4];
    #pragma unroll
    for (int i = 0; i < 4; i++)
        #pragma unroll
        for (int j = 0; j < 4; j++)
            #pragma unroll
            for (int r = 0; r < 4; r++) acc[i][j][r] = 0.f;

    // prologue: load slab 0 into buffer 0
    {
        const float* As = Ab + (size_t)lr * K + lc;
        const float* Ws = Wb + (size_t)lr * K + lc;
        uint32_t da = sbase + (uint32_t)((lr * PAD + lc) * 4);
        uint32_t db = sbase + 2u * TILE_BYTES + (uint32_t)((lr * PAD + lc) * 4);
        #pragma unroll
        for (int i = 0; i < 4; i++) {
            cp16(da + i * 16, As + i * 4);
            cp16(db + i * 16, Ws + i * 4);
        }
        cp_commit();
    }

    for (int s = 0; s < NS; s++) {
        const int b = s & 1;
        if (s + 1 < NS) {
            const int nb = (s + 1) & 1;
            const float* As = Ab + (size_t)lr * K + (s + 1) * BK + lc;
            const float* Ws = Wb + (size_t)lr * K + (s + 1) * BK + lc;
            uint32_t da = sbase + (uint32_t)nb * TILE_BYTES + (uint32_t)((lr * PAD + lc) * 4);
            uint32_t db = sbase + (2u + nb) * TILE_BYTES + (uint32_t)((lr * PAD + lc) * 4);
            #pragma unroll
            for (int i = 0; i < 4; i++) {
                cp16(da + i * 16, As + i * 4);
                cp16(db + i * 16, Ws + i * 4);
            }
            cp_commit();
            asm volatile("cp.async.wait_group 1;");
        } else {
            asm volatile("cp.async.wait_group 0;");
        }
        __syncthreads();

        const float* a_s = sm + b * TILE_F + (wm * 64 + g) * PAD;
        const float* b_s = sm + (2 + b) * TILE_F + (wn * 32 + g) * PAD;
        #pragma unroll
        for (int ks = 0; ks < 4; ks++) {
            const int kc = ks * 8 + q;
            uint32_t af[4][4];
            #pragma unroll
            for (int mf = 0; mf < 4; mf++) {
                const float* ap = a_s + mf * 16 * PAD;
                af[mf][0] = f2tf(ap[kc]);
                af[mf][1] = f2tf(ap[8 * PAD + kc]);
                af[mf][2] = f2tf(ap[kc + 4]);
                af[mf][3] = f2tf(ap[8 * PAD + kc + 4]);
            }
            uint32_t bf[4][2];
            #pragma unroll
            for (int nf = 0; nf < 4; nf++) {
                const float* bp = b_s + nf * 8 * PAD;
                bf[nf][0] = f2tf(bp[kc]);
                bf[nf][1] = f2tf(bp[kc + 4]);
            }
            #pragma unroll
            for (int mf = 0; mf < 4; mf++)
                #pragma unroll
                for (int nf = 0; nf < 4; nf++)
                    mma_tf32(acc[mf][nf], af[mf], bf[nf]);
        }
        __syncthreads();
    }

    // epilogue
    #pragma unroll
    for (int mf = 0; mf < 4; mf++) {
        #pragma unroll
        for (int nf = 0; nf < 4; nf++) {
            const int row = by * BM + wm * 64 + mf * 16 + g;
            const int col = bx * BN + wn * 32 + nf * 8 + q * 2;
            const float b0 = bias[col], b1 = bias[col + 1];
            float2 o0, o1;
            o0.x = (acc[mf][nf][0] + b0) * scale;
            o0.y = (acc[mf][nf][1] + b1) * scale;
            o1.x = (acc[mf][nf][2] + b0) * scale;
            o1.y = (acc[mf][nf][3] + b1) * scale;
            *(float2*)(C + (size_t)row * Ncols + col) = o0;
            *(float2*)(C + (size_t)(row + 8) * Ncols + col) = o1;
        }
    }
}

// ================= fp32 8x8 microkernel step (float4 LDS) =================
__device__ __forceinline__ void mk_step(const float* a, const float* b, float acc[8][8]) {
    float rm[8], rn[8];
    *(float4*)&rm[0] = *(const float4*)(a);
    *(float4*)&rm[4] = *(const float4*)(a + 4);
    *(float4*)&rn[0] = *(const float4*)(b);
    *(float4*)&rn[4] = *(const float4*)(b + 4);
    #pragma unroll
    for (int i = 0; i < 8; i++)
        #pragma unroll
        for (int j = 0; j < 8; j++)
            acc[i][j] += rm[i] * rn[j];
}

// ---------------- rotary (in-place on q and k) ----------------
__global__ void rotary_k(float* __restrict__ q, float* __restrict__ k,
                         const float* __restrict__ sn, const float* __restrict__ cs)
{
    int p = blockIdx.x * blockDim.x + threadIdx.x;
    if (p >= B_*T_*E_/2) return;
    int f = p * 2;
    int row = f / E_;
    int t = row % T_;
    int col = f % E_;
    int d = col % KD_;
    float2 qv = *(float2*)(q + (size_t)f);
    float2 kv = *(float2*)(k + (size_t)f);
    float c0 = cs[t*KD_ + d], c1 = cs[t*KD_ + d + 1];
    float s0 = sn[t*KD_ + d], s1 = sn[t*KD_ + d + 1];
    float2 qo, ko;
    qo.x = qv.x * c0 - qv.y * s0;
    qo.y = qv.y * c1 + qv.x * s1;
    ko.x = kv.x * c0 - kv.y * s0;
    ko.y = kv.y * c1 + kv.x * s1;
    *(float2*)(q + (size_t)f) = qo;
    *(float2*)(k + (size_t)f) = ko;
}

// ---------------- qk = qr @ kr^T * mask, plus row |.| sums ----------------
__global__ __launch_bounds__(512)
void qk_kernel(const float* __restrict__ mask)
{
    __shared__ float As[8][128];
    __shared__ float Bs[8][256];
    const int z = blockIdx.x;
    const int chunk = z >> 1, half = z & 1;
    const int b = chunk / (NC_*H_);
    const int n = (chunk / H_) % NC_;
    const int h = chunk % H_;
    const int row0 = half * 128;
    const int tid = threadIdx.x;
    const int tr = tid >> 5, tc = tid & 31;
    const float* Ab = g_q + ((size_t)(b*T_ + n*CH_ + row0)) * E_ + h*KD_;
    const float* Bb = g_k + ((size_t)(b*T_ + n*CH_)) * E_ + h*KD_;
    const int a_row = tid >> 2, a_k = (tid & 3) * 2;
    const int b_row = tid >> 1, b_k = (tid & 1) * 4;
    float acc[8][8] = {};
    for (int k0 = 0; k0 < KD_; k0 += 8) {
        float2 a2 = *(const float2*)(Ab + (size_t)a_row * E_ + k0 + a_k);
        float4 b4 = *(const float4*)(Bb + (size_t)b_row * E_ + k0 + b_k);
        As[a_k  ][a_row] = a2.x;
        As[a_k+1][a_row] = a2.y;
        Bs[b_k+0][b_row] = b4.x; Bs[b_k+1][b_row] = b4.y;
        Bs[b_k+2][b_row] = b4.z; Bs[b_k+3][b_row] = b4.w;
        __syncthreads();
        #pragma unroll
        for (int kk = 0; kk < 8; kk++) mk_step(&As[kk][tr*8], &Bs[kk][tc*8], acc);
        __syncthreads();
    }
    float* qko = g_qk + (size_t)chunk * (CH_*CH_) + (size_t)row0 * CH_;
    const float* mrow = mask + (size_t)h * (CH_*CH_) + (size_t)row0 * CH_;
    #pragma unroll
    for (int i = 0; i < 8; i++) {
        int r = tr*8 + i;
        float psum = 0.f;
        #pragma unroll
        for (int j = 0; j < 8; j++) {
            int c = tc*8 + j;
            float v = acc[i][j] * mrow[(size_t)r*CH_ + c];
            qko[(size_t)r*CH_ + c] = v;
            psum += fabsf(v);
        }
        #pragma unroll
        for (int o = 16; o > 0; o >>= 1)
            psum += __shfl_xor_sync(0xffffffffu, psum, o);
        if (tc == 0) g_isc[chunk*CH_ + row0 + r] = psum;
    }
}

// ---------------- inner = (qk / clip(isc,1)) @ vc ----------------
__global__ __launch_bounds__(512)
void inner_kernel()
{
    __shared__ float As[8][128];
    __shared__ float Bs[8][256];
    const int z = blockIdx.x;
    const int chunk = z >> 1, half = z & 1;
    const int b = chunk / (NC_*H_);
    const int n = (chunk / H_) % NC_;
    const int h = chunk % H_;
    const int row0 = half * 128;
    const int tid = threadIdx.x;
    const int tr = tid >> 5, tc = tid & 31;
    const float* Ab = g_qk + (size_t)chunk * (CH_*CH_) + (size_t)row0 * CH_;
    const float* Vb = g_v + ((size_t)(b*T_ + n*CH_)) * E2_ + h*HD_;
    const int a_row = tid >> 2, a_k = (tid & 3) * 2;
    const int bkk = tid >> 6, bv = (tid & 63) * 4;
    float acc[8][8] = {};
    for (int k0 = 0; k0 < CH_; k0 += 8) {
        float2 a2 = *(const float2*)(Ab + (size_t)a_row * CH_ + k0 + a_k);
        As[a_k  ][a_row] = a2.x;
        As[a_k+1][a_row] = a2.y;
        float4 b4 = *(const float4*)(Vb + (size_t)(k0 + bkk) * E2_ + bv);
        *(float4*)&Bs[bkk][bv] = b4;
        __syncthreads();
        #pragma unroll
        for (int kk = 0; kk < 8; kk++) mk_step(&As[kk][tr*8], &Bs[kk][tc*8], acc);
        __syncthreads();
    }
    float* op = g_inner + (size_t)chunk * (CH_*HD_) + (size_t)row0 * HD_;
    #pragma unroll
    for (int i = 0; i < 8; i++) {
        int r = tr*8 + i;
        float inv = 1.f / fmaxf(g_isc[chunk*CH_ + row0 + r], 1.f);
        #pragma unroll
        for (int j = 0; j < 8; j++)
            op[(size_t)r*HD_ + tc*8 + j] = acc[i][j] * inv;
    }
}

// ---------------- kv[k,v] = sum_c kr[c,k]*maskrow[c]*vc[c,v] ----------------
__global__ __launch_bounds__(512)
void kv_kernel(const float* __restrict__ mask)
{
    __shared__ float As[8][128];
    __shared__ float Bs[8][256];
    const int chunk = blockIdx.x;
    const int b = chunk / (NC_*H_);
    const int n = (chunk / H_) % NC_;
    const int h = chunk % H_;
    const int tid = threadIdx.x;
    const int tr = tid >> 5, tc = tid & 31;
    const float* Kb = g_k + ((size_t)(b*T_ + n*CH_)) * E_ + h*KD_;
    const float* Vb = g_v + ((size_t)(b*T_ + n*CH_)) * E2_ + h*HD_;
    const float* wrow = mask + (size_t)h * (CH_*CH_) + (size_t)(CH_-1) * CH_;
    const int acc_cc = tid >> 6;
    const int a_kcol = (tid & 63) * 2;
    const int b_vcol = (tid & 63) * 4;
    float acc[8][8] = {};
    for (int c0 = 0; c0 < CH_; c0 += 8) {
        float w = wrow[c0 + acc_cc];
        float2 a2 = *(const float2*)(Kb + (size_t)(c0 + acc_cc) * E_ + a_kcol);
        As[acc_cc][a_kcol  ] = a2.x * w;
        As[acc_cc][a_kcol+1] = a2.y * w;
        float4 b4 = *(const float4*)(Vb + (size_t)(c0 + acc_cc) * E2_ + b_vcol);
        *(float4*)&Bs[acc_cc][b_vcol] = b4;
        __syncthreads();
        #pragma unroll
        for (int kk = 0; kk < 8; kk++) mk_step(&As[kk][tr*8], &Bs[kk][tc*8], acc);
        __syncthreads();
    }
    float* op = g_kv + (size_t)chunk * (KD_*HD_);
    #pragma unroll
    for (int i = 0; i < 8; i++)
        #pragma unroll
        for (int j = 0; j < 8; j++)
            op[(size_t)(tr*8+i)*HD_ + tc*8 + j] = acc[i][j];
}

// ---------------- cross-chunk scan ----------------
__global__ __launch_bounds__(256)
void scan_kernel(const float* __restrict__ cdec)
{
    const int vb = blockIdx.x & 15;
    const int bh = blockIdx.x >> 4;
    const int b = bh / H_, h = bh % H_;
    const int v0 = vb * 16;
    const int tid = threadIdx.x;
    const int v = tid & 15;
    const int kg = tid >> 4;
    float s[8] = {0,0,0,0,0,0,0,0};
    __shared__ float sc[16];
    __shared__ float red[256];
    if (tid < 16) sc[tid] = 1.f;
    __syncthreads();
    const float cd = cdec[h];
    for (int n = 0; n < NC_; n++) {
        const int chunk = (b*NC_ + n)*H_ + h;
        const size_t zo = (size_t)chunk * (KD_*HD_);
        float invsc = 1.f / sc[v];
        #pragma unroll
        for (int i = 0; i < 8; i++)
            g_kvr[zo + (size_t)(kg*8+i)*HD_ + v0 + v] = s[i] * invsc;
        if (tid < 16) g_csc[chunk*HD_ + v0 + tid] = sc[tid];
        float p = 0.f;
        #pragma unroll
        for (int i = 0; i < 8; i++) {
            s[i] = s[i]*cd + g_kv[zo + (size_t)(kg*8+i)*HD_ + v0 + v];
            p += fabsf(s[i]);
        }
        red[tid] = p;
        __syncthreads();
        if (tid < 16) {
            float sum = 0.f;
            #pragma unroll
            for (int j = 0; j < 16; j++) sum += red[j*16 + tid];
            sc[tid] = fmaxf(sum, 1.f);
        }
        __syncthreads();
    }
}

// ------- cross = (qr*idec) @ kv_rec; combine + LayerNorm + silu(g) gate -------
__global__ __launch_bounds__(512)
void cross_kernel(const float* __restrict__ idec)
{
    __shared__ float As[8][128];
    __shared__ float Bs[8][256];
    const int z = blockIdx.x;
    const int chunk = z >> 1, half = z & 1;
    const int b = chunk / (NC_*H_);
    const int n = (chunk / H_) % NC_;
    const int h = chunk % H_;
    const int row0 = half * 128;
    const int tid = threadIdx.x;
    const int tr = tid >> 5, tc = tid & 31;
    const float* Ab = g_q + ((size_t)(b*T_ + n*CH_ + row0)) * E_ + h*KD_;
    const float* Bb = g_kvr + (size_t)chunk * (KD_*HD_);
    const int a_row = tid >> 2, a_k = (tid & 3) * 2;
    const int bkk = tid >> 6, bv = (tid & 63) * 4;
    const float aw = idec[h*CH_ + row0 + a_row];
    float acc[8][8] = {};
    for (int k0 = 0; k0 < KD_; k0 += 8) {
        float2 a2 = *(const float2*)(Ab + (size_t)a_row * E_ + k0 + a_k);
        As[a_k  ][a_row] = a2.x * aw;
        As[a_k+1][a_row] = a2.y * aw;
        float4 b4 = *(const float4*)(Bb + (size_t)(k0 + bkk) * HD_ + bv);
        *(float4*)&Bs[bkk][bv] = b4;
        __syncthreads();
        #pragma unroll
        for (int kk = 0; kk < 8; kk++) mk_step(&As[kk][tr*8], &Bs[kk][tc*8], acc);
        __syncthreads();
    }
    const float* innp = g_inner + (size_t)chunk * (CH_*HD_) + (size_t)row0 * HD_;
    const float* cscp = g_csc + chunk*HD_;
    const float* gp   = g_gt + ((size_t)(b*T_ + n*CH_ + row0)) * E2_ + h*HD_;
    float* rop        = g_ro + ((size_t)(b*T_ + n*CH_ + row0)) * E2_ + h*HD_;
    #pragma unroll
    for (int i = 0; i < 8; i++) {
        int r = tr*8 + i;
        float isc = fmaxf(g_isc[chunk*CH_ + row0 + r], 1.f);
        float rsum = 0.f, rsq = 0.f;
        #pragma unroll
        for (int j = 0; j < 8; j++) {
            int c = tc*8 + j;
            float o = innp[(size_t)r*HD_ + c] / cscp[c] + acc[i][j] / isc;
            acc[i][j] = o;
            rsum += o;
            rsq  += o*o;
        }
        #pragma unroll
        for (int off = 16; off > 0; off >>= 1) {
            rsum += __shfl_xor_sync(0xffffffffu, rsum, off);
            rsq  += __shfl_xor_sync(0xffffffffu, rsq,  off);
        }
        float mean = rsum * (1.f/HD_);
        float var  = rsq  * (1.f/HD_) - mean*mean;
        float rstd = rsqrtf(var + 1e-5f);
        #pragma unroll
        for (int j = 0; j < 8; j++) {
            int c = tc*8 + j;
            float gv = gp[(size_t)r*E2_ + c];
            float si = gv / (1.f + expf(-gv));
            rop[(size_t)r*E2_ + c] = si * (acc[i][j] - mean) * rstd;
        }
    }
}

// ================= launch =================
extern "C" void kernel_launch(void* const* d_in, const int* in_sizes, int n_in,
                              void* d_out, int out_size)
{
    const float* x    = (const float*)d_in[0];
    const float* sn   = (const float*)d_in[1];
    const float* cs   = (const float*)d_in[2];
    const float* mask = (const float*)d_in[3];
    const float* cdec = (const float*)d_in[4];
    const float* idec = (const float*)d_in[5];
    const float* Wq = (const float*)d_in[6];
    const float* bq = (const float*)d_in[7];
    const float* Wk = (const float*)d_in[8];
    const float* bk = (const float*)d_in[9];
    const float* Wv = (const float*)d_in[10];
    const float* bv = (const float*)d_in[11];
    const float* Wg = (const float*)d_in[12];
    const float* bg = (const float*)d_in[13];
    const float* Wo = (const float*)d_in[14];
    const float* bo = (const float*)d_in[15];
    float* out = (float*)d_out;

    float *qp, *kp, *vp, *gp, *rop;
    cudaGetSymbolAddress((void**)&qp,  g_q);
    cudaGetSymbolAddress((void**)&kp,  g_k);
    cudaGetSymbolAddress((void**)&vp,  g_v);
    cudaGetSymbolAddress((void**)&gp,  g_gt);
    cudaGetSymbolAddress((void**)&rop, g_ro);

    cudaFuncSetAttribute(gemm_mma, cudaFuncAttributeMaxDynamicSharedMemorySize, GEMM_SMEM);

    const int M = B_*T_;
    const float kscale = 1.0f / sqrtf((float)KD_);

    gemm_mma<<<dim3(E_/BN,  M/BM), 256, GEMM_SMEM>>>(x, Wq, bq, qp, E_,  E_,  1.f);
    gemm_mma<<<dim3(E_/BN,  M/BM), 256, GEMM_SMEM>>>(x, Wk, bk, kp, E_,  E_,  kscale);
    gemm_mma<<<dim3(E2_/BN, M/BM), 256, GEMM_SMEM>>>(x, Wv, bv, vp, E_,  E2_, 1.f);
    gemm_mma<<<dim3(E2_/BN, M/BM), 256, GEMM_SMEM>>>(x, Wg, bg, gp, E_,  E2_, 1.f);
    rotary_k<<<(B_*T_*E_/2 + 255)/256, 256>>>(qp, kp, sn, cs);
    qk_kernel   <<<2*NCHUNKS, 512>>>(mask);
    inner_kernel<<<2*NCHUNKS, 512>>>();
    kv_kernel   <<<NCHUNKS,   512>>>(mask);
    scan_kernel <<<B_*H_*(HD_/16), 256>>>(cdec);
    cross_kernel<<<2*NCHUNKS, 512>>>(idec);
    gemm_mma<<<dim3(E_/BN, M/BM), 256, GEMM_SMEM>>>(rop, Wo, bo, out, E2_, E_, 1.f);
}

// round 4
// speedup vs baseline: 3.7857x; 1.5809x over previous
#include <cuda_runtime.h>
#include <cuda_fp16.h>
#include <math.h>
#include <stdint.h>

#define B_ 2
#define T_ 4096
#define E_ 2048
#define E2_ 4096
#define H_ 16
#define KD_ 128
#define HD_ 256
#define CH_ 256
#define NC_ 16
#define NCHUNKS (B_*NC_*H_)   // 512

// ================= scratch =================
__device__ float g_q [B_*T_*E_];
__device__ float g_k [B_*T_*E_];
__device__ float g_v [B_*T_*E2_];
__device__ float g_gt[B_*T_*E2_];
__device__ float g_qk[(size_t)NCHUNKS*CH_*CH_];
__device__ float g_isc[NCHUNKS*CH_];
__device__ float g_inner[(size_t)NCHUNKS*CH_*HD_];
__device__ float g_kv [(size_t)NCHUNKS*KD_*HD_];
__device__ float g_kvr[(size_t)NCHUNKS*KD_*HD_];
__device__ float g_csc[NCHUNKS*HD_];
// half-precision staging
__device__ __half g_xh [B_*T_*E_];
__device__ __half g_roh[B_*T_*E2_];
__device__ __half g_wqh[E_*E_];
__device__ __half g_wkh[E_*E_];
__device__ __half g_wvh[(size_t)E2_*E_];
__device__ __half g_wgh[(size_t)E2_*E_];
__device__ __half g_woh[(size_t)E_*E2_];

// ================= helpers =================
__device__ __forceinline__ uint32_t smem_u32(const void* p) {
    uint32_t a;
    asm("{ .reg .u64 t; cvta.to.shared.u64 t, %1; cvt.u32.u64 %0, t; }" : "=r"(a) : "l"(p));
    return a;
}
__device__ __forceinline__ void cp16(uint32_t dst, const void* src) {
    asm volatile("cp.async.cg.shared.global [%0], [%1], 16;" :: "r"(dst), "l"(src));
}
__device__ __forceinline__ void cp_commit() { asm volatile("cp.async.commit_group;"); }
__device__ __forceinline__ void ldm_x4(uint32_t r[4], uint32_t addr) {
    asm volatile("ldmatrix.sync.aligned.m8n8.x4.shared.b16 {%0,%1,%2,%3}, [%4];"
        : "=r"(r[0]), "=r"(r[1]), "=r"(r[2]), "=r"(r[3]) : "r"(addr));
}
__device__ __forceinline__ void mma_f16(float c[4], const uint32_t a[4], const uint32_t b[2]) {
    asm volatile(
        "mma.sync.aligned.m16n8k16.row.col.f32.f16.f16.f32 "
        "{%0,%1,%2,%3}, {%4,%5,%6,%7}, {%8,%9}, {%0,%1,%2,%3};"
        : "+f"(c[0]), "+f"(c[1]), "+f"(c[2]), "+f"(c[3])
        : "r"(a[0]), "r"(a[1]), "r"(a[2]), "r"(a[3]), "r"(b[0]), "r"(b[1]));
}

// ================= f32 -> f16 converter =================
__global__ void f2h(const float* __restrict__ in, __half* __restrict__ out, int n4)
{
    int i = blockIdx.x * blockDim.x + threadIdx.x;
    if (i >= n4) return;
    float4 v = *(const float4*)(in + (size_t)i * 4);
    __half2 h[2];
    h[0] = __floats2half2_rn(v.x, v.y);
    h[1] = __floats2half2_rn(v.z, v.w);
    *(uint2*)(out + (size_t)i * 4) = *(uint2*)h;
}

// ================= fp16 tensor-core GEMM: C = (A @ W^T + bias) * scale =================
// A [M,K] half row-major, W [N,K] half row-major. Block 128x128, K-slab 64.
// 8 warps 2(M) x 4(N); warp tile 64x32; mma m16n8k16 + ldmatrix.
#define BKH 64
#define PADH 72                       // halfs per row (144 B)
#define TILEH (128*PADH*2)            // 18432 B
#define GEMMH_SMEM (4*TILEH)          // 73728 B

__global__ void __launch_bounds__(256)
gemm_h(const __half* __restrict__ A, const __half* __restrict__ W,
       const float* __restrict__ bias, float* __restrict__ C,
       int K, int Ncols, float scale)
{
    extern __shared__ __align__(128) char smh[];
    const int tid = threadIdx.x;
    const int wid = tid >> 5, lane = tid & 31;
    const int wm = wid & 1, wn = wid >> 1;
    const int g = lane >> 2, q = lane & 3;
    const int bx = blockIdx.x, by = blockIdx.y;

    const __half* Ab = A + (size_t)(by * 128) * K;
    const __half* Wb = W + (size_t)(bx * 128) * K;
    const uint32_t sb = smem_u32(smh);

    // loader mapping: 128 rows x 64 halfs; 8 cp16 units per row
    const int lr  = tid >> 1;
    const int lcu = (tid & 1) * 4;

    // ldmatrix lane addressing
    const int lrow8 = (lane & 7) + ((lane >> 3) & 1) * 8;  // 0..15
    const int koffB = (lane >> 4) * 16;                    // 0 or 16 bytes

    float acc[4][4][4] = {};

    // prologue: slab 0 -> buffer 0
    {
        const __half* As = Ab + (size_t)lr * K + lcu * 8;
        const __half* Ws = Wb + (size_t)lr * K + lcu * 8;
        uint32_t da = sb + (uint32_t)(lr * 144 + lcu * 16);
        uint32_t db = sb + 2u * TILEH + (uint32_t)(lr * 144 + lcu * 16);
        #pragma unroll
        for (int i = 0; i < 4; i++) { cp16(da + i * 16, As + i * 8); cp16(db + i * 16, Ws + i * 8); }
        cp_commit();
    }

    const int NS = K / BKH;
    for (int s = 0; s < NS; s++) {
        const int b = s & 1;
        if (s + 1 < NS) {
            const int nb = (s + 1) & 1;
            const __half* As = Ab + (size_t)lr * K + (s + 1) * BKH + lcu * 8;
            const __half* Ws = Wb + (size_t)lr * K + (s + 1) * BKH + lcu * 8;
            uint32_t da = sb + (uint32_t)nb * TILEH + (uint32_t)(lr * 144 + lcu * 16);
            uint32_t db = sb + (2u + nb) * TILEH + (uint32_t)(lr * 144 + lcu * 16);
            #pragma unroll
            for (int i = 0; i < 4; i++) { cp16(da + i * 16, As + i * 8); cp16(db + i * 16, Ws + i * 8); }
            cp_commit();
            asm volatile("cp.async.wait_group 1;");
        } else {
            asm volatile("cp.async.wait_group 0;");
        }
        __syncthreads();

        const uint32_t a_base = sb + (uint32_t)b * TILEH + (uint32_t)((wm * 64 + lrow8) * 144 + koffB);
        const uint32_t b_base = sb + 2u * TILEH + (uint32_t)b * TILEH + (uint32_t)((wn * 32 + lrow8) * 144 + koffB);
        #pragma unroll
        for (int ks = 0; ks < 4; ks++) {
            const uint32_t kc2 = ks * 32;    // 16 halfs per k-step
            uint32_t af[4][4];
            #pragma unroll
            for (int mf = 0; mf < 4; mf++) ldm_x4(af[mf], a_base + mf * 16 * 144 + kc2);
            uint32_t bf[4][2];
            #pragma unroll
            for (int nf2 = 0; nf2 < 2; nf2++) {
                uint32_t t4[4];
                ldm_x4(t4, b_base + nf2 * 16 * 144 + kc2);
                bf[2*nf2  ][0] = t4[0]; bf[2*nf2  ][1] = t4[2];
                bf[2*nf2+1][0] = t4[1]; bf[2*nf2+1][1] = t4[3];
            }
            #pragma unroll
            for (int mf = 0; mf < 4; mf++)
                #pragma unroll
                for (int nf = 0; nf < 4; nf++)
                    mma_f16(acc[mf][nf], af[mf], bf[nf]);
        }
        __syncthreads();
    }

    // epilogue
    #pragma unroll
    for (int mf = 0; mf < 4; mf++) {
        #pragma unroll
        for (int nf = 0; nf < 4; nf++) {
            const int row = by * 128 + wm * 64 + mf * 16 + g;
            const int col = bx * 128 + wn * 32 + nf * 8 + q * 2;
            const float b0 = bias[col], b1 = bias[col + 1];
            float2 o0, o1;
            o0.x = (acc[mf][nf][0] + b0) * scale;
            o0.y = (acc[mf][nf][1] + b1) * scale;
            o1.x = (acc[mf][nf][2] + b0) * scale;
            o1.y = (acc[mf][nf][3] + b1) * scale;
            *(float2*)(C + (size_t)row * Ncols + col) = o0;
            *(float2*)(C + (size_t)(row + 8) * Ncols + col) = o1;
        }
    }
}

// ================= fp32 8x8 microkernel step (float4 LDS) =================
__device__ __forceinline__ void mk_step(const float* a, const float* b, float acc[8][8]) {
    float rm[8], rn[8];
    *(float4*)&rm[0] = *(const float4*)(a);
    *(float4*)&rm[4] = *(const float4*)(a + 4);
    *(float4*)&rn[0] = *(const float4*)(b);
    *(float4*)&rn[4] = *(const float4*)(b + 4);
    #pragma unroll
    for (int i = 0; i < 8; i++)
        #pragma unroll
        for (int j = 0; j < 8; j++)
            acc[i][j] += rm[i] * rn[j];
}

// ---------------- rotary (in-place on q and k) ----------------
__global__ void rotary_k(float* __restrict__ q, float* __restrict__ k,
                         const float* __restrict__ sn, const float* __restrict__ cs)
{
    int p = blockIdx.x * blockDim.x + threadIdx.x;
    if (p >= B_*T_*E_/2) return;
    int f = p * 2;
    int row = f / E_;
    int t = row % T_;
    int col = f % E_;
    int d = col % KD_;
    float2 qv = *(float2*)(q + (size_t)f);
    float2 kv = *(float2*)(k + (size_t)f);
    float c0 = cs[t*KD_ + d], c1 = cs[t*KD_ + d + 1];
    float s0 = sn[t*KD_ + d], s1 = sn[t*KD_ + d + 1];
    float2 qo, ko;
    qo.x = qv.x * c0 - qv.y * s0;
    qo.y = qv.y * c1 + qv.x * s1;
    ko.x = kv.x * c0 - kv.y * s0;
    ko.y = kv.y * c1 + kv.x * s1;
    *(float2*)(q + (size_t)f) = qo;
    *(float2*)(k + (size_t)f) = ko;
}

// ---------------- qk = qr @ kr^T * mask, plus row |.| sums ----------------
__global__ __launch_bounds__(512)
void qk_kernel(const float* __restrict__ mask)
{
    __shared__ float As[8][128];
    __shared__ float Bs[8][256];
    const int z = blockIdx.x;
    const int chunk = z >> 1, half = z & 1;
    const int b = chunk / (NC_*H_);
    const int n = (chunk / H_) % NC_;
    const int h = chunk % H_;
    const int row0 = half * 128;
    const int tid = threadIdx.x;
    const int tr = tid >> 5, tc = tid & 31;
    const float* Ab = g_q + ((size_t)(b*T_ + n*CH_ + row0)) * E_ + h*KD_;
    const float* Bb = g_k + ((size_t)(b*T_ + n*CH_)) * E_ + h*KD_;
    const int a_row = tid >> 2, a_k = (tid & 3) * 2;
    const int b_row = tid >> 1, b_k = (tid & 1) * 4;
    float acc[8][8] = {};
    for (int k0 = 0; k0 < KD_; k0 += 8) {
        float2 a2 = *(const float2*)(Ab + (size_t)a_row * E_ + k0 + a_k);
        float4 b4 = *(const float4*)(Bb + (size_t)b_row * E_ + k0 + b_k);
        As[a_k  ][a_row] = a2.x;
        As[a_k+1][a_row] = a2.y;
        Bs[b_k+0][b_row] = b4.x; Bs[b_k+1][b_row] = b4.y;
        Bs[b_k+2][b_row] = b4.z; Bs[b_k+3][b_row] = b4.w;
        __syncthreads();
        #pragma unroll
        for (int kk = 0; kk < 8; kk++) mk_step(&As[kk][tr*8], &Bs[kk][tc*8], acc);
        __syncthreads();
    }
    float* qko = g_qk + (size_t)chunk * (CH_*CH_) + (size_t)row0 * CH_;
    const float* mrow = mask + (size_t)h * (CH_*CH_) + (size_t)row0 * CH_;
    #pragma unroll
    for (int i = 0; i < 8; i++) {
        int r = tr*8 + i;
        float psum = 0.f;
        #pragma unroll
        for (int j = 0; j < 8; j++) {
            int c = tc*8 + j;
            float v = acc[i][j] * mrow[(size_t)r*CH_ + c];
            qko[(size_t)r*CH_ + c] = v;
            psum += fabsf(v);
        }
        #pragma unroll
        for (int o = 16; o > 0; o >>= 1)
            psum += __shfl_xor_sync(0xffffffffu, psum, o);
        if (tc == 0) g_isc[chunk*CH_ + row0 + r] = psum;
    }
}

// ---------------- inner = (qk / clip(isc,1)) @ vc ----------------
__global__ __launch_bounds__(512)
void inner_kernel()
{
    __shared__ float As[8][128];
    __shared__ float Bs[8][256];
    const int z = blockIdx.x;
    const int chunk = z >> 1, half = z & 1;
    const int b = chunk / (NC_*H_);
    const int n = (chunk / H_) % NC_;
    const int h = chunk % H_;
    const int row0 = half * 128;
    const int tid = threadIdx.x;
    const int tr = tid >> 5, tc = tid & 31;
    const float* Ab = g_qk + (size_t)chunk * (CH_*CH_) + (size_t)row0 * CH_;
    const float* Vb = g_v + ((size_t)(b*T_ + n*CH_)) * E2_ + h*HD_;
    const int a_row = tid >> 2, a_k = (tid & 3) * 2;
    const int bkk = tid >> 6, bv = (tid & 63) * 4;
    float acc[8][8] = {};
    for (int k0 = 0; k0 < CH_; k0 += 8) {
        float2 a2 = *(const float2*)(Ab + (size_t)a_row * CH_ + k0 + a_k);
        As[a_k  ][a_row] = a2.x;
        As[a_k+1][a_row] = a2.y;
        float4 b4 = *(const float4*)(Vb + (size_t)(k0 + bkk) * E2_ + bv);
        *(float4*)&Bs[bkk][bv] = b4;
        __syncthreads();
        #pragma unroll
        for (int kk = 0; kk < 8; kk++) mk_step(&As[kk][tr*8], &Bs[kk][tc*8], acc);
        __syncthreads();
    }
    float* op = g_inner + (size_t)chunk * (CH_*HD_) + (size_t)row0 * HD_;
    #pragma unroll
    for (int i = 0; i < 8; i++) {
        int r = tr*8 + i;
        float inv = 1.f / fmaxf(g_isc[chunk*CH_ + row0 + r], 1.f);
        #pragma unroll
        for (int j = 0; j < 8; j++)
            op[(size_t)r*HD_ + tc*8 + j] = acc[i][j] * inv;
    }
}

// ---------------- kv[k,v] = sum_c kr[c,k]*maskrow[c]*vc[c,v] ----------------
__global__ __launch_bounds__(512)
void kv_kernel(const float* __restrict__ mask)
{
    __shared__ float As[8][128];
    __shared__ float Bs[8][256];
    const int chunk = blockIdx.x;
    const int b = chunk / (NC_*H_);
    const int n = (chunk / H_) % NC_;
    const int h = chunk % H_;
    const int tid = threadIdx.x;
    const int tr = tid >> 5, tc = tid & 31;
    const float* Kb = g_k + ((size_t)(b*T_ + n*CH_)) * E_ + h*KD_;
    const float* Vb = g_v + ((size_t)(b*T_ + n*CH_)) * E2_ + h*HD_;
    const float* wrow = mask + (size_t)h * (CH_*CH_) + (size_t)(CH_-1) * CH_;
    const int acc_cc = tid >> 6;
    const int a_kcol = (tid & 63) * 2;
    const int b_vcol = (tid & 63) * 4;
    float acc[8][8] = {};
    for (int c0 = 0; c0 < CH_; c0 += 8) {
        float w = wrow[c0 + acc_cc];
        float2 a2 = *(const float2*)(Kb + (size_t)(c0 + acc_cc) * E_ + a_kcol);
        As[acc_cc][a_kcol  ] = a2.x * w;
        As[acc_cc][a_kcol+1] = a2.y * w;
        float4 b4 = *(const float4*)(Vb + (size_t)(c0 + acc_cc) * E2_ + b_vcol);
        *(float4*)&Bs[acc_cc][b_vcol] = b4;
        __syncthreads();
        #pragma unroll
        for (int kk = 0; kk < 8; kk++) mk_step(&As[kk][tr*8], &Bs[kk][tc*8], acc);
        __syncthreads();
    }
    float* op = g_kv + (size_t)chunk * (KD_*HD_);
    #pragma unroll
    for (int i = 0; i < 8; i++)
        #pragma unroll
        for (int j = 0; j < 8; j++)
            op[(size_t)(tr*8+i)*HD_ + tc*8 + j] = acc[i][j];
}

// ---------------- cross-chunk scan ----------------
__global__ __launch_bounds__(256)
void scan_kernel(const float* __restrict__ cdec)
{
    const int vb = blockIdx.x & 15;
    const int bh = blockIdx.x >> 4;
    const int b = bh / H_, h = bh % H_;
    const int v0 = vb * 16;
    const int tid = threadIdx.x;
    const int v = tid & 15;
    const int kg = tid >> 4;
    float s[8] = {0,0,0,0,0,0,0,0};
    __shared__ float sc[16];
    __shared__ float red[256];
    if (tid < 16) sc[tid] = 1.f;
    __syncthreads();
    const float cd = cdec[h];
    for (int n = 0; n < NC_; n++) {
        const int chunk = (b*NC_ + n)*H_ + h;
        const size_t zo = (size_t)chunk * (KD_*HD_);
        float invsc = 1.f / sc[v];
        #pragma unroll
        for (int i = 0; i < 8; i++)
            g_kvr[zo + (size_t)(kg*8+i)*HD_ + v0 + v] = s[i] * invsc;
        if (tid < 16) g_csc[chunk*HD_ + v0 + tid] = sc[tid];
        float p = 0.f;
        #pragma unroll
        for (int i = 0; i < 8; i++) {
            s[i] = s[i]*cd + g_kv[zo + (size_t)(kg*8+i)*HD_ + v0 + v];
            p += fabsf(s[i]);
        }
        red[tid] = p;
        __syncthreads();
        if (tid < 16) {
            float sum = 0.f;
            #pragma unroll
            for (int j = 0; j < 16; j++) sum += red[j*16 + tid];
            sc[tid] = fmaxf(sum, 1.f);
        }
        __syncthreads();
    }
}

// ------- cross = (qr*idec) @ kv_rec; combine + LN + silu(g) gate -> half -------
__global__ __launch_bounds__(512)
void cross_kernel(const float* __restrict__ idec)
{
    __shared__ float As[8][128];
    __shared__ float Bs[8][256];
    const int z = blockIdx.x;
    const int chunk = z >> 1, half = z & 1;
    const int b = chunk / (NC_*H_);
    const int n = (chunk / H_) % NC_;
    const int h = chunk % H_;
    const int row0 = half * 128;
    const int tid = threadIdx.x;
    const int tr = tid >> 5, tc = tid & 31;
    const float* Ab = g_q + ((size_t)(b*T_ + n*CH_ + row0)) * E_ + h*KD_;
    const float* Bb = g_kvr + (size_t)chunk * (KD_*HD_);
    const int a_row = tid >> 2, a_k = (tid & 3) * 2;
    const int bkk = tid >> 6, bv = (tid & 63) * 4;
    const float aw = idec[h*CH_ + row0 + a_row];
    float acc[8][8] = {};
    for (int k0 = 0; k0 < KD_; k0 += 8) {
        float2 a2 = *(const float2*)(Ab + (size_t)a_row * E_ + k0 + a_k);
        As[a_k  ][a_row] = a2.x * aw;
        As[a_k+1][a_row] = a2.y * aw;
        float4 b4 = *(const float4*)(Bb + (size_t)(k0 + bkk) * HD_ + bv);
        *(float4*)&Bs[bkk][bv] = b4;
        __syncthreads();
        #pragma unroll
        for (int kk = 0; kk < 8; kk++) mk_step(&As[kk][tr*8], &Bs[kk][tc*8], acc);
        __syncthreads();
    }
    const float* innp = g_inner + (size_t)chunk * (CH_*HD_) + (size_t)row0 * HD_;
    const float* cscp = g_csc + chunk*HD_;
    const float* gp   = g_gt + ((size_t)(b*T_ + n*CH_ + row0)) * E2_ + h*HD_;
    __half* rop       = g_roh + ((size_t)(b*T_ + n*CH_ + row0)) * E2_ + h*HD_;
    #pragma unroll
    for (int i = 0; i < 8; i++) {
        int r = tr*8 + i;
        float isc = fmaxf(g_isc[chunk*CH_ + row0 + r], 1.f);
        float rsum = 0.f, rsq = 0.f;
        #pragma unroll
        for (int j = 0; j < 8; j++) {
            int c = tc*8 + j;
            float o = innp[(size_t)r*HD_ + c] / cscp[c] + acc[i][j] / isc;
            acc[i][j] = o;
            rsum += o;
            rsq  += o*o;
        }
        #pragma unroll
        for (int off = 16; off > 0; off >>= 1) {
            rsum += __shfl_xor_sync(0xffffffffu, rsum, off);
            rsq  += __shfl_xor_sync(0xffffffffu, rsq,  off);
        }
        float mean = rsum * (1.f/HD_);
        float var  = rsq  * (1.f/HD_) - mean*mean;
        float rstd = rsqrtf(var + 1e-5f);
        __half2 hv[4];
        #pragma unroll
        for (int j = 0; j < 8; j += 2) {
            int c = tc*8 + j;
            float gv0 = gp[(size_t)r*E2_ + c];
            float gv1 = gp[(size_t)r*E2_ + c + 1];
            float o0 = (gv0 / (1.f + expf(-gv0))) * (acc[i][j]   - mean) * rstd;
            float o1 = (gv1 / (1.f + expf(-gv1))) * (acc[i][j+1] - mean) * rstd;
            hv[j>>1] = __floats2half2_rn(o0, o1);
        }
        *(uint2*)(rop + (size_t)r*E2_ + tc*8)     = *(uint2*)&hv[0];
        *(uint2*)(rop + (size_t)r*E2_ + tc*8 + 4) = *(uint2*)&hv[2];
    }
}

// ================= launch =================
extern "C" void kernel_launch(void* const* d_in, const int* in_sizes, int n_in,
                              void* d_out, int out_size)
{
    const float* x    = (const float*)d_in[0];
    const float* sn   = (const float*)d_in[1];
    const float* cs   = (const float*)d_in[2];
    const float* mask = (const float*)d_in[3];
    const float* cdec = (const float*)d_in[4];
    const float* idec = (const float*)d_in[5];
    const float* Wq = (const float*)d_in[6];
    const float* bq = (const float*)d_in[7];
    const float* Wk = (const float*)d_in[8];
    const float* bk = (const float*)d_in[9];
    const float* Wv = (const float*)d_in[10];
    const float* bv = (const float*)d_in[11];
    const float* Wg = (const float*)d_in[12];
    const float* bg = (const float*)d_in[13];
    const float* Wo = (const float*)d_in[14];
    const float* bo = (const float*)d_in[15];
    float* out = (float*)d_out;

    float *qp, *kp, *vp, *gp;
    __half *xh, *roh, *wqh, *wkh, *wvh, *wgh, *woh;
    cudaGetSymbolAddress((void**)&qp,  g_q);
    cudaGetSymbolAddress((void**)&kp,  g_k);
    cudaGetSymbolAddress((void**)&vp,  g_v);
    cudaGetSymbolAddress((void**)&gp,  g_gt);
    cudaGetSymbolAddress((void**)&xh,  g_xh);
    cudaGetSymbolAddress((void**)&roh, g_roh);
    cudaGetSymbolAddress((void**)&wqh, g_wqh);
    cudaGetSymbolAddress((void**)&wkh, g_wkh);
    cudaGetSymbolAddress((void**)&wvh, g_wvh);
    cudaGetSymbolAddress((void**)&wgh, g_wgh);
    cudaGetSymbolAddress((void**)&woh, g_woh);

    cudaFuncSetAttribute(gemm_h, cudaFuncAttributeMaxDynamicSharedMemorySize, GEMMH_SMEM);

    const int M = B_*T_;
    const float kscale = 1.0f / sqrtf((float)KD_);

    // f32 -> f16 staging
    f2h<<<(M*E_/4 + 255)/256, 256>>>(x, xh, M*E_/4);
    f2h<<<(E_*E_/4 + 255)/256, 256>>>(Wq, wqh, E_*E_/4);
    f2h<<<(E_*E_/4 + 255)/256, 256>>>(Wk, wkh, E_*E_/4);
    f2h<<<(E2_*E_/4 + 255)/256, 256>>>(Wv, wvh, E2_*E_/4);
    f2h<<<(E2_*E_/4 + 255)/256, 256>>>(Wg, wgh, E2_*E_/4);
    f2h<<<(E_*E2_/4 + 255)/256, 256>>>(Wo, woh, E_*E2_/4);

    gemm_h<<<dim3(E_/128,  M/128), 256, GEMMH_SMEM>>>(xh, wqh, bq, qp, E_,  E_,  1.f);
    gemm_h<<<dim3(E_/128,  M/128), 256, GEMMH_SMEM>>>(xh, wkh, bk, kp, E_,  E_,  kscale);
    gemm_h<<<dim3(E2_/128, M/128), 256, GEMMH_SMEM>>>(xh, wvh, bv, vp, E_,  E2_, 1.f);
    gemm_h<<<dim3(E2_/128, M/128), 256, GEMMH_SMEM>>>(xh, wgh, bg, gp, E_,  E2_, 1.f);
    rotary_k<<<(B_*T_*E_/2 + 255)/256, 256>>>(qp, kp, sn, cs);
    qk_kernel   <<<2*NCHUNKS, 512>>>(mask);
    inner_kernel<<<2*NCHUNKS, 512>>>();
    kv_kernel   <<<NCHUNKS,   512>>>(mask);
    scan_kernel <<<B_*H_*(HD_/16), 256>>>(cdec);
    cross_kernel<<<2*NCHUNKS, 512>>>(idec);
    gemm_h<<<dim3(E_/128, M/128), 256, GEMMH_SMEM>>>(roh, woh, bo, out, E2_, E_, 1.f);
}